// round 7
// baseline (speedup 1.0000x reference)
#include <cuda_runtime.h>
#include <cstdint>

// ----------------------------------------------------------------------------
// Decoder_61237643706389 — fused trilinear MLP decoder, fp32x2 (FFMA2) path.
// Round 7: thread tile flipped to 8ch x 4u (was 4ch x 8u) to halve SMEM
// crossbar requested bytes (the measured binder: L1 72% from broadcast-
// duplicated LDS). Weights pre-duplicated into u64 pairs in global memory
// (prep kernel) so the inner loop has ZERO pack movs: per kstep/thread =
// 16 FFMA2 + 4 LDG.128 + 1 LDS.128 + 2 IADD.
// ----------------------------------------------------------------------------

#define G        32
#define NBATCH   2
#define CCH      96
#define NPTS     32768          // points per batch (32^3)
#define OUTC     45
#define NCOORD   78
#define NP       4              // points per block
#define NU       32             // units per block (NP * 8 corners)
#define PAD      36             // row stride in floats (32 units + 4 pad, 144B)
#define THREADS  96

// Transposed context features: [B][x][y][z][C], contiguous C — 25.2 MB scratch.
__device__ float g_cvt[NBATCH * NPTS * CCH];

typedef unsigned long long u64;

// Duplicated weights: each element (w,w) as u64. Layout per layer, per k-row:
//   u64 index = layer_base + k*96 + p*24 + jg*2 + e,   (p=0..3, jg=0..11, e=0..1)
// i.e. channel c = 8*jg + 2*p + e. Each warp's LDG.128 #p then covers one
// 128B line (jg*16B within a 64B-aligned group).
#define WD_L0   0
#define WD_L1   16704           // 174*96
#define WD_L2   25920           // + 96*96
#define WD_L3   35136
#define WD_L4   51840           // + 174*96
#define WD_L5   61056
#define WD_TOT  70272
__device__ u64 g_wdup[WD_TOT];

__device__ __forceinline__ u64 pack2(float lo, float hi) {
    u64 r; asm("mov.b64 %0, {%1, %2};" : "=l"(r) : "f"(lo), "f"(hi)); return r;
}
__device__ __forceinline__ void unpack2(u64 v, float& lo, float& hi) {
    asm("mov.b64 {%0, %1}, %2;" : "=f"(lo), "=f"(hi) : "l"(v));
}
__device__ __forceinline__ u64 ffma2(u64 a, u64 b, u64 c) {
    u64 d; asm("fma.rn.f32x2 %0, %1, %2, %3;" : "=l"(d) : "l"(a), "l"(b), "l"(c));
    return d;
}
__device__ __forceinline__ float silu_f(float x) {
    return x / (1.0f + __expf(-x));
}

// ---------------------------------------------------------------------------
// Weight duplication prep: src [K,96] f32 -> g_wdup[base + k*96 + p*24 + jg*2 + e]
// ---------------------------------------------------------------------------
__global__ void dup_weights(const float* __restrict__ src, int base, int K) {
    int idx = blockIdx.x * blockDim.x + threadIdx.x;
    if (idx >= K * CCH) return;
    int k = idx / CCH, c = idx % CCH;
    int jg = c >> 3, p = (c >> 1) & 3, e = c & 1;
    float v = src[idx];
    g_wdup[base + k * 96 + p * 24 + jg * 2 + e] = pack2(v, v);
}

// ---------------------------------------------------------------------------
// Transpose context_v [B,C,S] -> g_cvt [B,S,C], S = 32^3. Tiled via SMEM.
// ---------------------------------------------------------------------------
__global__ void transpose_ctx(const float* __restrict__ src) {
    __shared__ float tile[CCH][65];          // pad 64->65 kills bank conflicts
    int bs = blockIdx.x;                     // 0 .. NBATCH*512-1
    int b  = bs >> 9;
    int s0 = (bs & 511) * 64;
    for (int idx = threadIdx.x; idx < CCH * 64; idx += blockDim.x) {
        int c = idx >> 6, so = idx & 63;
        tile[c][so] = src[((long)(b * CCH + c) << 15) + s0 + so];
    }
    __syncthreads();
    for (int idx = threadIdx.x; idx < CCH * 64; idx += blockDim.x) {
        int so = idx / CCH, c = idx % CCH;
        g_cvt[(((long)b << 15) + s0 + so) * CCH + c] = tile[c][so];
    }
}

// ---------------------------------------------------------------------------
// One k-step from preloaded operands: 8 channels x 4 units = 16 FFMA2, 0 movs.
// ---------------------------------------------------------------------------
__device__ __forceinline__ void kcompute(ulonglong2 w0, ulonglong2 w1,
                                         ulonglong2 w2, ulonglong2 w3,
                                         double2 h, u64 (&acc)[8][2]) {
    u64 h0 = __double_as_longlong(h.x);
    u64 h1 = __double_as_longlong(h.y);
    acc[0][0] = ffma2(h0, w0.x, acc[0][0]); acc[0][1] = ffma2(h1, w0.x, acc[0][1]);
    acc[1][0] = ffma2(h0, w0.y, acc[1][0]); acc[1][1] = ffma2(h1, w0.y, acc[1][1]);
    acc[2][0] = ffma2(h0, w1.x, acc[2][0]); acc[2][1] = ffma2(h1, w1.x, acc[2][1]);
    acc[3][0] = ffma2(h0, w1.y, acc[3][0]); acc[3][1] = ffma2(h1, w1.y, acc[3][1]);
    acc[4][0] = ffma2(h0, w2.x, acc[4][0]); acc[4][1] = ffma2(h1, w2.x, acc[4][1]);
    acc[5][0] = ffma2(h0, w2.y, acc[5][0]); acc[5][1] = ffma2(h1, w2.y, acc[5][1]);
    acc[6][0] = ffma2(h0, w3.x, acc[6][0]); acc[6][1] = ffma2(h1, w3.x, acc[6][1]);
    acc[7][0] = ffma2(h0, w3.y, acc[7][0]); acc[7][1] = ffma2(h1, w3.y, acc[7][1]);
}

// ---------------------------------------------------------------------------
// Distance-1 pipelined partial GEMM.
// wp: thread's duplicated-weight slot (u64 index jg*2 into a k-row of 96 u64;
//     p-blocks at +24 u64). hp: thread's 4-unit slice (row stride PAD).
// ---------------------------------------------------------------------------
template <int K>
__device__ __forceinline__ void gemm_part(const u64* __restrict__ wp,
                                          const float* hp, u64 (&acc)[8][2]) {
    ulonglong2 w0 = __ldg(reinterpret_cast<const ulonglong2*>(wp));
    ulonglong2 w1 = __ldg(reinterpret_cast<const ulonglong2*>(wp + 24));
    ulonglong2 w2 = __ldg(reinterpret_cast<const ulonglong2*>(wp + 48));
    ulonglong2 w3 = __ldg(reinterpret_cast<const ulonglong2*>(wp + 72));
    double2 h = *reinterpret_cast<const double2*>(hp);
    wp += 96; hp += PAD;

#pragma unroll 2
    for (int k = 0; k < K - 1; ++k) {
        ulonglong2 n0 = __ldg(reinterpret_cast<const ulonglong2*>(wp));
        ulonglong2 n1 = __ldg(reinterpret_cast<const ulonglong2*>(wp + 24));
        ulonglong2 n2 = __ldg(reinterpret_cast<const ulonglong2*>(wp + 48));
        ulonglong2 n3 = __ldg(reinterpret_cast<const ulonglong2*>(wp + 72));
        double2 hn = *reinterpret_cast<const double2*>(hp);
        wp += 96; hp += PAD;
        kcompute(w0, w1, w2, w3, h, acc);
        w0 = n0; w1 = n1; w2 = n2; w3 = n3; h = hn;
    }
    kcompute(w0, w1, w2, w3, h, acc);
}

// Linear layer (K1 rows from s1, optional K2 rows from s2) + silu + residual.
// Activations layout: [96 channels][PAD units].
// Thread (jg, ug) owns channels 8jg..8jg+7, units 4ug..4ug+3.
template <int K1, int K2, bool RES>
__device__ __forceinline__ void mlp_layer(const u64* __restrict__ Wd,
                                          const float* __restrict__ Bv,
                                          const float* s1, const float* s2,
                                          float* dst, const float* resid,
                                          int jg, int ug) {
    u64 acc[8][2];
#pragma unroll
    for (int ch = 0; ch < 8; ++ch) {
        float bv = __ldg(Bv + 8 * jg + ch);
        acc[ch][0] = acc[ch][1] = pack2(bv, bv);
    }

    gemm_part<K1>(Wd + jg * 2, s1 + 4 * ug, acc);
    if (K2 > 0)
        gemm_part<(K2 > 0 ? K2 : 1)>(Wd + K1 * 96 + jg * 2, s2 + 4 * ug, acc);

#pragma unroll
    for (int ch = 0; ch < 8; ++ch) {
        float x0, x1, x2, x3;
        unpack2(acc[ch][0], x0, x1);
        unpack2(acc[ch][1], x2, x3);
        float4 o;
        o.x = silu_f(x0); o.y = silu_f(x1); o.z = silu_f(x2); o.w = silu_f(x3);
        int off = (8 * jg + ch) * PAD + 4 * ug;
        if (RES) {
            float4 r4 = *reinterpret_cast<const float4*>(resid + off);
            o.x += r4.x; o.y += r4.y; o.z += r4.z; o.w += r4.w;
        }
        *reinterpret_cast<float4*>(dst + off) = o;
    }
}

// ---------------------------------------------------------------------------
// Main kernel: each block = 4 points x 8 corners = 32 units, 96 threads.
// ---------------------------------------------------------------------------
__global__ void __launch_bounds__(THREADS, 4)
decoder_kernel(const float* __restrict__ qw_g,
               const int* __restrict__ mask_g,
               const float* __restrict__ grid_g,
               const float* __restrict__ affine_g,
               const float* __restrict__ b00, const float* __restrict__ b01,
               const float* __restrict__ b02, const float* __restrict__ b10,
               const float* __restrict__ b11, const float* __restrict__ b12,
               const float* __restrict__ wpo, const float* __restrict__ bpo,
               float* __restrict__ out) {
    const int tid = threadIdx.x;
    const int pg0 = blockIdx.x * NP;         // first global point of group
    const int b   = pg0 >> 15;               // batch (groups never straddle)

    extern __shared__ float smem[];
    float* s_y = smem;                       // [96][PAD]
    float* s_a = s_y + CCH * PAD;            // [96][PAD]
    float* s_b = s_a + CCH * PAD;            // [96][PAD]
    float* s_c = s_b + CCH * PAD;            // [78][PAD]

    __shared__ float s_inv[12];              // rows 0..2 of inv(affine)
    __shared__ float s_qw[NP][3];
    __shared__ float s_sub[NP][3];
    __shared__ float s_mf[NP];
    __shared__ int   s_bot[NP][3];
    __shared__ int   s_voff[NU];
    __shared__ float s_cw[NU][3];
    __shared__ float s_wtri[NU];

    // --- phase 1: affine inverse (last row assumed [0,0,0,1]) ---
    if (tid == 0) {
        const float* A = affine_g + b * 16;
        float a00 = A[0], a01 = A[1], a02 = A[2],  t0 = A[3];
        float a10 = A[4], a11 = A[5], a12 = A[6],  t1 = A[7];
        float a20 = A[8], a21 = A[9], a22 = A[10], t2 = A[11];
        float c00 = a11 * a22 - a12 * a21;
        float c01 = a02 * a21 - a01 * a22;
        float c02 = a01 * a12 - a02 * a11;
        float det = a00 * c00 + a10 * c01 + a20 * c02;
        float id  = 1.0f / det;
        float i00 = c00 * id, i01 = c01 * id, i02 = c02 * id;
        float i10 = (a12 * a20 - a10 * a22) * id;
        float i11 = (a00 * a22 - a02 * a20) * id;
        float i12 = (a02 * a10 - a00 * a12) * id;
        float i20 = (a10 * a21 - a11 * a20) * id;
        float i21 = (a01 * a20 - a00 * a21) * id;
        float i22 = (a00 * a11 - a01 * a10) * id;
        s_inv[0] = i00; s_inv[1] = i01; s_inv[2]  = i02; s_inv[3]  = -(i00 * t0 + i01 * t1 + i02 * t2);
        s_inv[4] = i10; s_inv[5] = i11; s_inv[6]  = i12; s_inv[7]  = -(i10 * t0 + i11 * t1 + i12 * t2);
        s_inv[8] = i20; s_inv[9] = i21; s_inv[10] = i22; s_inv[11] = -(i20 * t0 + i21 * t1 + i22 * t2);
    }
    __syncthreads();

    // --- phase 2: per-point setup ---
    if (tid < NP) {
        int pg = pg0 + tid;
        float mf = (mask_g[pg] != 0) ? 1.0f : 0.0f;
        const float* qp = qw_g + (mf != 0.0f ? (long)pg * 3
                                             : ((long)b * NPTS + NPTS / 2) * 3);
        float q0 = qp[0], q1 = qp[1], q2 = qp[2];
        s_qw[tid][0] = q0; s_qw[tid][1] = q1; s_qw[tid][2] = q2;
        s_mf[tid] = mf;
#pragma unroll
        for (int r = 0; r < 3; ++r) {
            float qv = s_inv[r * 4 + 0] * q0 + s_inv[r * 4 + 1] * q1 +
                       s_inv[r * 4 + 2] * q2 + s_inv[r * 4 + 3];
            float fb = floorf(qv);
            s_bot[tid][r] = (int)fb;
            s_sub[tid][r] = qv - fb;
        }
    }
    __syncthreads();

    // --- phase 3: per-unit voxel offset, cw gather, trilinear weight ---
    if (tid < NU) {
        int pt = tid >> 3, c = tid & 7;
        int o0 = (c >> 2) & 1, o1 = (c >> 1) & 1, o2 = c & 1;
        int i0 = min(max(s_bot[pt][0] + o0, 0), G - 1);
        int i1 = min(max(s_bot[pt][1] + o1, 0), G - 1);
        int i2 = min(max(s_bot[pt][2] + o2, 0), G - 1);
        int sp = (i0 * G + i1) * G + i2;
        s_voff[tid] = (b * NPTS + sp) * CCH;
        const float* gp = grid_g + (long)(b * NPTS + sp) * 3;
        s_cw[tid][0] = gp[0]; s_cw[tid][1] = gp[1]; s_cw[tid][2] = gp[2];
        float ww0 = o0 ? s_sub[pt][0] : 1.0f - s_sub[pt][0];
        float ww1 = o1 ? s_sub[pt][1] : 1.0f - s_sub[pt][1];
        float ww2 = o2 ? s_sub[pt][2] : 1.0f - s_sub[pt][2];
        s_wtri[tid] = ww0 * ww1 * ww2;
    }
    __syncthreads();

    // --- phase 4: feature gather + coordinate encoding ---
#pragma unroll 8
    for (int u = 0; u < NU; ++u) {
        float mf = s_mf[u >> 3];
        s_y[tid * PAD + u] = g_cvt[s_voff[u] + tid] * mf;
    }
    // coord rows 0..5: cw, qw   (192 entries)
#pragma unroll
    for (int it = 0; it < 2; ++it) {
        int idx = tid + it * THREADS;        // < 192
        int u = idx / 6, r = idx % 6;
        float mf = s_mf[u >> 3];
        float v = (r < 3) ? s_cw[u][r] : s_qw[u >> 3][r - 3];
        s_c[r * PAD + u] = v * mf;
    }
    // coord rows 6..77: fourier encoding (32 units x 3 axes x 12 freqs)
#pragma unroll
    for (int it = 0; it < 12; ++it) {
        int idx = tid + it * THREADS;        // < 1152
        int u = idx / 36, e = idx % 36;
        int a = e / 12, j = e % 12;
        int pt = u >> 3, c = u & 7;
        int off = (a == 0) ? ((c >> 2) & 1) : ((a == 1) ? ((c >> 1) & 1) : (c & 1));
        float rel = (s_sub[pt][a] - (float)off + 1.0f) * 0.5f;
        float f = exp2f((float)j * 0.13208020839342967f);   // 3^(j/12)
        float ang = 6.283185307179586f * f * rel;
        float sv, cv;
        __sincosf(ang, &sv, &cv);
        float mf = s_mf[pt];
        s_c[(6 + a * 24 + j) * PAD + u]      = sv * mf;
        s_c[(6 + a * 24 + 12 + j) * PAD + u] = cv * mf;
    }
    __syncthreads();

    // --- MLP: 2 x SkipMLPBlock (duplicated weights in g_wdup) ---
    const int jg = tid >> 3;   // channel group 0..11 (8 channels each)
    const int ug = tid & 7;    // unit group   0..7  (4 units each)

    mlp_layer<96, 78, false>(g_wdup + WD_L0, b00, s_y, s_c, s_a, nullptr, jg, ug); __syncthreads();
    mlp_layer<96, 0,  false>(g_wdup + WD_L1, b01, s_a, nullptr, s_b, nullptr, jg, ug); __syncthreads();
    mlp_layer<96, 0,  true >(g_wdup + WD_L2, b02, s_b, nullptr, s_y, s_y,     jg, ug); __syncthreads();
    mlp_layer<96, 78, false>(g_wdup + WD_L3, b10, s_y, s_c, s_a, nullptr, jg, ug); __syncthreads();
    mlp_layer<96, 0,  false>(g_wdup + WD_L4, b11, s_a, nullptr, s_b, nullptr, jg, ug); __syncthreads();
    mlp_layer<96, 0,  true >(g_wdup + WD_L5, b12, s_b, nullptr, s_y, s_y,     jg, ug); __syncthreads();

    // --- trilinear reduce across the 8 corners: ybar = sum_c wtri_c * y_c ---
    // (sum_c wtri_c == 1, so the post-GEMM applies once per point)
#pragma unroll
    for (int it = 0; it < 4; ++it) {
        int idx = tid + it * THREADS;        // < 384
        int ch = idx >> 2, pt = idx & 3;
        float acc = 0.0f;
#pragma unroll
        for (int c = 0; c < 8; ++c)
            acc += s_wtri[pt * 8 + c] * s_y[ch * PAD + pt * 8 + c];
        s_a[ch * PAD + pt] = acc;
    }
    __syncthreads();

    // --- post layer: 96 -> 45, 4 points ---
    if (tid < OUTC) {
        float a0 = bpo[tid], a1 = a0, a2 = a0, a3 = a0;
#pragma unroll 4
        for (int k = 0; k < CCH; ++k) {
            float w = __ldg(wpo + k * OUTC + tid);
            a0 = fmaf(s_a[k * PAD + 0], w, a0);
            a1 = fmaf(s_a[k * PAD + 1], w, a1);
            a2 = fmaf(s_a[k * PAD + 2], w, a2);
            a3 = fmaf(s_a[k * PAD + 3], w, a3);
        }
        int n0 = pg0 & (NPTS - 1);
        long base = ((long)b * OUTC + tid) * NPTS + n0;
        out[base]     = a0;
        out[base + 1] = a1;
        out[base + 2] = a2;
        out[base + 3] = a3;
    }
}

// ---------------------------------------------------------------------------
extern "C" void kernel_launch(void* const* d_in, const int* in_sizes, int n_in,
                              void* d_out, int out_size) {
    const float* context_v = (const float*)d_in[0];
    const float* grid      = (const float*)d_in[1];
    const float* qw        = (const float*)d_in[2];
    const int*   mask      = (const int*)d_in[3];
    const float* affine    = (const float*)d_in[4];
    const float* w00 = (const float*)d_in[8],  *b00 = (const float*)d_in[9];
    const float* w01 = (const float*)d_in[10], *b01 = (const float*)d_in[11];
    const float* w02 = (const float*)d_in[12], *b02 = (const float*)d_in[13];
    const float* w10 = (const float*)d_in[14], *b10 = (const float*)d_in[15];
    const float* w11 = (const float*)d_in[16], *b11 = (const float*)d_in[17];
    const float* w12 = (const float*)d_in[18], *b12 = (const float*)d_in[19];
    const float* wpo = (const float*)d_in[20], *bpo = (const float*)d_in[21];
    float* out = (float*)d_out;

    const int smem_bytes = (CCH * 3 + NCOORD) * PAD * sizeof(float);  // 52704
    static int configured = 0;
    if (!configured) {
        cudaFuncSetAttribute(decoder_kernel,
                             cudaFuncAttributeMaxDynamicSharedMemorySize,
                             smem_bytes);
        configured = 1;
    }

    transpose_ctx<<<NBATCH * 512, 256>>>(context_v);

    // weight duplication (tiny)
    dup_weights<<<(174 * CCH + 255) / 256, 256>>>(w00, WD_L0, 174);
    dup_weights<<<( 96 * CCH + 255) / 256, 256>>>(w01, WD_L1, 96);
    dup_weights<<<( 96 * CCH + 255) / 256, 256>>>(w02, WD_L2, 96);
    dup_weights<<<(174 * CCH + 255) / 256, 256>>>(w10, WD_L3, 174);
    dup_weights<<<( 96 * CCH + 255) / 256, 256>>>(w11, WD_L4, 96);
    dup_weights<<<( 96 * CCH + 255) / 256, 256>>>(w12, WD_L5, 96);

    // 65536 points total, 4 points (32 point-corner units) per block
    decoder_kernel<<<(NBATCH * NPTS) / NP, THREADS, smem_bytes>>>(
        qw, mask, grid, affine,
        b00, b01, b02, b10, b11, b12,
        wpo, bpo, out);
}

// round 8
// speedup vs baseline: 1.1416x; 1.1416x over previous
#include <cuda_runtime.h>
#include <cstdint>

// ----------------------------------------------------------------------------
// Decoder_61237643706389 — fused trilinear MLP decoder, fp32x2 (FFMA2) path.
// Round 8: 8ch x 4u thread tile (halves LDS phases vs 4ch x 8u: 1 LDS.128
// instead of 2 per kstep) with PLAIN weights (2x LDG.128 of the original
// [k][96] rows, duplicated into FFMA2 lanes via in-register movs).
// r7's gmem-duplicated weights doubled the weight footprint and regressed;
// this keeps the 298KB weight stream L1-friendly.
// Per kstep/thread: 2 LDG.128 + 1 LDS.128 + 8 movs + 16 FFMA2.
// L1 per warp-kstep: 6 ops (was 9) -> fma pipe becomes the binder.
// ----------------------------------------------------------------------------

#define G        32
#define NBATCH   2
#define CCH      96
#define NPTS     32768          // points per batch (32^3)
#define OUTC     45
#define NCOORD   78
#define NP       4              // points per block
#define NU       32             // units per block (NP * 8 corners)
#define PAD      36             // row stride in floats (32 units + 4 pad, 144B)
#define THREADS  96

// Transposed context features: [B][x][y][z][C], contiguous C — 25.2 MB scratch.
__device__ float g_cvt[NBATCH * NPTS * CCH];

typedef unsigned long long u64;

__device__ __forceinline__ u64 pack2(float lo, float hi) {
    u64 r; asm("mov.b64 %0, {%1, %2};" : "=l"(r) : "f"(lo), "f"(hi)); return r;
}
__device__ __forceinline__ void unpack2(u64 v, float& lo, float& hi) {
    asm("mov.b64 {%0, %1}, %2;" : "=f"(lo), "=f"(hi) : "l"(v));
}
__device__ __forceinline__ u64 ffma2(u64 a, u64 b, u64 c) {
    u64 d; asm("fma.rn.f32x2 %0, %1, %2, %3;" : "=l"(d) : "l"(a), "l"(b), "l"(c));
    return d;
}
__device__ __forceinline__ float silu_f(float x) {
    return x / (1.0f + __expf(-x));
}

// ---------------------------------------------------------------------------
// Transpose context_v [B,C,S] -> g_cvt [B,S,C], S = 32^3. Tiled via SMEM.
// ---------------------------------------------------------------------------
__global__ void transpose_ctx(const float* __restrict__ src) {
    __shared__ float tile[CCH][65];          // pad 64->65 kills bank conflicts
    int bs = blockIdx.x;                     // 0 .. NBATCH*512-1
    int b  = bs >> 9;
    int s0 = (bs & 511) * 64;
    for (int idx = threadIdx.x; idx < CCH * 64; idx += blockDim.x) {
        int c = idx >> 6, so = idx & 63;
        tile[c][so] = src[((long)(b * CCH + c) << 15) + s0 + so];
    }
    __syncthreads();
    for (int idx = threadIdx.x; idx < CCH * 64; idx += blockDim.x) {
        int so = idx / CCH, c = idx % CCH;
        g_cvt[(((long)b << 15) + s0 + so) * CCH + c] = tile[c][so];
    }
}

// ---------------------------------------------------------------------------
// One k-step from preloaded operands: 8 channels x 4 units = 16 FFMA2.
// FFMA2 lanes hold unit pairs (u0,u1) / (u2,u3); w duplicated via movs.
// ---------------------------------------------------------------------------
__device__ __forceinline__ void kcompute(float4 wA, float4 wB, double2 h,
                                         u64 (&acc)[8][2]) {
    u64 h01 = __double_as_longlong(h.x);
    u64 h23 = __double_as_longlong(h.y);
    u64 wd;
    wd = pack2(wA.x, wA.x); acc[0][0] = ffma2(h01, wd, acc[0][0]); acc[0][1] = ffma2(h23, wd, acc[0][1]);
    wd = pack2(wA.y, wA.y); acc[1][0] = ffma2(h01, wd, acc[1][0]); acc[1][1] = ffma2(h23, wd, acc[1][1]);
    wd = pack2(wA.z, wA.z); acc[2][0] = ffma2(h01, wd, acc[2][0]); acc[2][1] = ffma2(h23, wd, acc[2][1]);
    wd = pack2(wA.w, wA.w); acc[3][0] = ffma2(h01, wd, acc[3][0]); acc[3][1] = ffma2(h23, wd, acc[3][1]);
    wd = pack2(wB.x, wB.x); acc[4][0] = ffma2(h01, wd, acc[4][0]); acc[4][1] = ffma2(h23, wd, acc[4][1]);
    wd = pack2(wB.y, wB.y); acc[5][0] = ffma2(h01, wd, acc[5][0]); acc[5][1] = ffma2(h23, wd, acc[5][1]);
    wd = pack2(wB.z, wB.z); acc[6][0] = ffma2(h01, wd, acc[6][0]); acc[6][1] = ffma2(h23, wd, acc[6][1]);
    wd = pack2(wB.w, wB.w); acc[7][0] = ffma2(h01, wd, acc[7][0]); acc[7][1] = ffma2(h23, wd, acc[7][1]);
}

// ---------------------------------------------------------------------------
// Distance-1 pipelined partial GEMM.
// wp: W + k*96 + 8*jg (plain layout). hp: thread's 4-unit slice, stride PAD.
// ---------------------------------------------------------------------------
template <int K>
__device__ __forceinline__ void gemm_part(const float* __restrict__ wp,
                                          const float* hp, u64 (&acc)[8][2]) {
    float4  wA = __ldg(reinterpret_cast<const float4*>(wp));
    float4  wB = __ldg(reinterpret_cast<const float4*>(wp + 4));
    double2 h  = *reinterpret_cast<const double2*>(hp);
    wp += CCH; hp += PAD;

#pragma unroll 2
    for (int k = 0; k < K - 1; ++k) {
        float4  wAn = __ldg(reinterpret_cast<const float4*>(wp));
        float4  wBn = __ldg(reinterpret_cast<const float4*>(wp + 4));
        double2 hn  = *reinterpret_cast<const double2*>(hp);
        wp += CCH; hp += PAD;
        kcompute(wA, wB, h, acc);
        wA = wAn; wB = wBn; h = hn;
    }
    kcompute(wA, wB, h, acc);
}

// Linear layer (K1 rows from s1, optional K2 rows from s2) + silu + residual.
// Activations layout: [96 channels][PAD units].
// Thread (jg, ug) owns channels 8jg..8jg+7, units 4ug..4ug+3.
template <int K1, int K2, bool RES>
__device__ __forceinline__ void mlp_layer(const float* __restrict__ W,
                                          const float* __restrict__ Bv,
                                          const float* s1, const float* s2,
                                          float* dst, const float* resid,
                                          int jg, int ug) {
    u64 acc[8][2];
#pragma unroll
    for (int ch = 0; ch < 8; ++ch) {
        float bv = __ldg(Bv + 8 * jg + ch);
        acc[ch][0] = acc[ch][1] = pack2(bv, bv);
    }

    gemm_part<K1>(W + 8 * jg, s1 + 4 * ug, acc);
    if (K2 > 0)
        gemm_part<(K2 > 0 ? K2 : 2)>(W + K1 * CCH + 8 * jg, s2 + 4 * ug, acc);

#pragma unroll
    for (int ch = 0; ch < 8; ++ch) {
        float x0, x1, x2, x3;
        unpack2(acc[ch][0], x0, x1);
        unpack2(acc[ch][1], x2, x3);
        float4 o;
        o.x = silu_f(x0); o.y = silu_f(x1); o.z = silu_f(x2); o.w = silu_f(x3);
        int off = (8 * jg + ch) * PAD + 4 * ug;
        if (RES) {
            float4 r4 = *reinterpret_cast<const float4*>(resid + off);
            o.x += r4.x; o.y += r4.y; o.z += r4.z; o.w += r4.w;
        }
        *reinterpret_cast<float4*>(dst + off) = o;
    }
}

// ---------------------------------------------------------------------------
// Main kernel: each block = 4 points x 8 corners = 32 units, 96 threads.
// ---------------------------------------------------------------------------
__global__ void __launch_bounds__(THREADS, 4)
decoder_kernel(const float* __restrict__ qw_g,
               const int* __restrict__ mask_g,
               const float* __restrict__ grid_g,
               const float* __restrict__ affine_g,
               const float* __restrict__ w00, const float* __restrict__ b00,
               const float* __restrict__ w01, const float* __restrict__ b01,
               const float* __restrict__ w02, const float* __restrict__ b02,
               const float* __restrict__ w10, const float* __restrict__ b10,
               const float* __restrict__ w11, const float* __restrict__ b11,
               const float* __restrict__ w12, const float* __restrict__ b12,
               const float* __restrict__ wpo, const float* __restrict__ bpo,
               float* __restrict__ out) {
    const int tid = threadIdx.x;
    const int pg0 = blockIdx.x * NP;         // first global point of group
    const int b   = pg0 >> 15;               // batch (groups never straddle)

    extern __shared__ float smem[];
    float* s_y = smem;                       // [96][PAD]
    float* s_a = s_y + CCH * PAD;            // [96][PAD]
    float* s_b = s_a + CCH * PAD;            // [96][PAD]
    float* s_c = s_b + CCH * PAD;            // [78][PAD]

    __shared__ float s_inv[12];              // rows 0..2 of inv(affine)
    __shared__ float s_qw[NP][3];
    __shared__ float s_sub[NP][3];
    __shared__ float s_mf[NP];
    __shared__ int   s_bot[NP][3];
    __shared__ int   s_voff[NU];
    __shared__ float s_cw[NU][3];
    __shared__ float s_wtri[NU];

    // --- phase 1: affine inverse (last row assumed [0,0,0,1]) ---
    if (tid == 0) {
        const float* A = affine_g + b * 16;
        float a00 = A[0], a01 = A[1], a02 = A[2],  t0 = A[3];
        float a10 = A[4], a11 = A[5], a12 = A[6],  t1 = A[7];
        float a20 = A[8], a21 = A[9], a22 = A[10], t2 = A[11];
        float c00 = a11 * a22 - a12 * a21;
        float c01 = a02 * a21 - a01 * a22;
        float c02 = a01 * a12 - a02 * a11;
        float det = a00 * c00 + a10 * c01 + a20 * c02;
        float id  = 1.0f / det;
        float i00 = c00 * id, i01 = c01 * id, i02 = c02 * id;
        float i10 = (a12 * a20 - a10 * a22) * id;
        float i11 = (a00 * a22 - a02 * a20) * id;
        float i12 = (a02 * a10 - a00 * a12) * id;
        float i20 = (a10 * a21 - a11 * a20) * id;
        float i21 = (a01 * a20 - a00 * a21) * id;
        float i22 = (a00 * a11 - a01 * a10) * id;
        s_inv[0] = i00; s_inv[1] = i01; s_inv[2]  = i02; s_inv[3]  = -(i00 * t0 + i01 * t1 + i02 * t2);
        s_inv[4] = i10; s_inv[5] = i11; s_inv[6]  = i12; s_inv[7]  = -(i10 * t0 + i11 * t1 + i12 * t2);
        s_inv[8] = i20; s_inv[9] = i21; s_inv[10] = i22; s_inv[11] = -(i20 * t0 + i21 * t1 + i22 * t2);
    }
    __syncthreads();

    // --- phase 2: per-point setup ---
    if (tid < NP) {
        int pg = pg0 + tid;
        float mf = (mask_g[pg] != 0) ? 1.0f : 0.0f;
        const float* qp = qw_g + (mf != 0.0f ? (long)pg * 3
                                             : ((long)b * NPTS + NPTS / 2) * 3);
        float q0 = qp[0], q1 = qp[1], q2 = qp[2];
        s_qw[tid][0] = q0; s_qw[tid][1] = q1; s_qw[tid][2] = q2;
        s_mf[tid] = mf;
#pragma unroll
        for (int r = 0; r < 3; ++r) {
            float qv = s_inv[r * 4 + 0] * q0 + s_inv[r * 4 + 1] * q1 +
                       s_inv[r * 4 + 2] * q2 + s_inv[r * 4 + 3];
            float fb = floorf(qv);
            s_bot[tid][r] = (int)fb;
            s_sub[tid][r] = qv - fb;
        }
    }
    __syncthreads();

    // --- phase 3: per-unit voxel offset, cw gather, trilinear weight ---
    if (tid < NU) {
        int pt = tid >> 3, c = tid & 7;
        int o0 = (c >> 2) & 1, o1 = (c >> 1) & 1, o2 = c & 1;
        int i0 = min(max(s_bot[pt][0] + o0, 0), G - 1);
        int i1 = min(max(s_bot[pt][1] + o1, 0), G - 1);
        int i2 = min(max(s_bot[pt][2] + o2, 0), G - 1);
        int sp = (i0 * G + i1) * G + i2;
        s_voff[tid] = (b * NPTS + sp) * CCH;
        const float* gp = grid_g + (long)(b * NPTS + sp) * 3;
        s_cw[tid][0] = gp[0]; s_cw[tid][1] = gp[1]; s_cw[tid][2] = gp[2];
        float ww0 = o0 ? s_sub[pt][0] : 1.0f - s_sub[pt][0];
        float ww1 = o1 ? s_sub[pt][1] : 1.0f - s_sub[pt][1];
        float ww2 = o2 ? s_sub[pt][2] : 1.0f - s_sub[pt][2];
        s_wtri[tid] = ww0 * ww1 * ww2;
    }
    __syncthreads();

    // --- phase 4: feature gather + coordinate encoding ---
#pragma unroll 8
    for (int u = 0; u < NU; ++u) {
        float mf = s_mf[u >> 3];
        s_y[tid * PAD + u] = g_cvt[s_voff[u] + tid] * mf;
    }
    // coord rows 0..5: cw, qw   (192 entries)
#pragma unroll
    for (int it = 0; it < 2; ++it) {
        int idx = tid + it * THREADS;        // < 192
        int u = idx / 6, r = idx % 6;
        float mf = s_mf[u >> 3];
        float v = (r < 3) ? s_cw[u][r] : s_qw[u >> 3][r - 3];
        s_c[r * PAD + u] = v * mf;
    }
    // coord rows 6..77: fourier encoding (32 units x 3 axes x 12 freqs)
#pragma unroll
    for (int it = 0; it < 12; ++it) {
        int idx = tid + it * THREADS;        // < 1152
        int u = idx / 36, e = idx % 36;
        int a = e / 12, j = e % 12;
        int pt = u >> 3, c = u & 7;
        int off = (a == 0) ? ((c >> 2) & 1) : ((a == 1) ? ((c >> 1) & 1) : (c & 1));
        float rel = (s_sub[pt][a] - (float)off + 1.0f) * 0.5f;
        float f = exp2f((float)j * 0.13208020839342967f);   // 3^(j/12)
        float ang = 6.283185307179586f * f * rel;
        float sv, cv;
        __sincosf(ang, &sv, &cv);
        float mf = s_mf[pt];
        s_c[(6 + a * 24 + j) * PAD + u]      = sv * mf;
        s_c[(6 + a * 24 + 12 + j) * PAD + u] = cv * mf;
    }
    __syncthreads();

    // --- MLP: 2 x SkipMLPBlock ---
    const int jg = tid >> 3;   // channel group 0..11 (8 channels each)
    const int ug = tid & 7;    // unit group   0..7  (4 units each)

    mlp_layer<96, 78, false>(w00, b00, s_y, s_c, s_a, nullptr, jg, ug); __syncthreads();
    mlp_layer<96, 0,  false>(w01, b01, s_a, nullptr, s_b, nullptr, jg, ug); __syncthreads();
    mlp_layer<96, 0,  true >(w02, b02, s_b, nullptr, s_y, s_y,     jg, ug); __syncthreads();
    mlp_layer<96, 78, false>(w10, b10, s_y, s_c, s_a, nullptr, jg, ug); __syncthreads();
    mlp_layer<96, 0,  false>(w11, b11, s_a, nullptr, s_b, nullptr, jg, ug); __syncthreads();
    mlp_layer<96, 0,  true >(w12, b12, s_b, nullptr, s_y, s_y,     jg, ug); __syncthreads();

    // --- trilinear reduce across the 8 corners: ybar = sum_c wtri_c * y_c ---
    // (sum_c wtri_c == 1, so the post-GEMM applies once per point)
#pragma unroll
    for (int it = 0; it < 4; ++it) {
        int idx = tid + it * THREADS;        // < 384
        int ch = idx >> 2, pt = idx & 3;
        float acc = 0.0f;
#pragma unroll
        for (int c = 0; c < 8; ++c)
            acc += s_wtri[pt * 8 + c] * s_y[ch * PAD + pt * 8 + c];
        s_a[ch * PAD + pt] = acc;
    }
    __syncthreads();

    // --- post layer: 96 -> 45, 4 points ---
    if (tid < OUTC) {
        float a0 = bpo[tid], a1 = a0, a2 = a0, a3 = a0;
#pragma unroll 4
        for (int k = 0; k < CCH; ++k) {
            float w = __ldg(wpo + k * OUTC + tid);
            a0 = fmaf(s_a[k * PAD + 0], w, a0);
            a1 = fmaf(s_a[k * PAD + 1], w, a1);
            a2 = fmaf(s_a[k * PAD + 2], w, a2);
            a3 = fmaf(s_a[k * PAD + 3], w, a3);
        }
        int n0 = pg0 & (NPTS - 1);
        long base = ((long)b * OUTC + tid) * NPTS + n0;
        out[base]     = a0;
        out[base + 1] = a1;
        out[base + 2] = a2;
        out[base + 3] = a3;
    }
}

// ---------------------------------------------------------------------------
extern "C" void kernel_launch(void* const* d_in, const int* in_sizes, int n_in,
                              void* d_out, int out_size) {
    const float* context_v = (const float*)d_in[0];
    const float* grid      = (const float*)d_in[1];
    const float* qw        = (const float*)d_in[2];
    const int*   mask      = (const int*)d_in[3];
    const float* affine    = (const float*)d_in[4];
    const float* w00 = (const float*)d_in[8],  *b00 = (const float*)d_in[9];
    const float* w01 = (const float*)d_in[10], *b01 = (const float*)d_in[11];
    const float* w02 = (const float*)d_in[12], *b02 = (const float*)d_in[13];
    const float* w10 = (const float*)d_in[14], *b10 = (const float*)d_in[15];
    const float* w11 = (const float*)d_in[16], *b11 = (const float*)d_in[17];
    const float* w12 = (const float*)d_in[18], *b12 = (const float*)d_in[19];
    const float* wpo = (const float*)d_in[20], *bpo = (const float*)d_in[21];
    float* out = (float*)d_out;

    const int smem_bytes = (CCH * 3 + NCOORD) * PAD * sizeof(float);  // 52704
    static int configured = 0;
    if (!configured) {
        cudaFuncSetAttribute(decoder_kernel,
                             cudaFuncAttributeMaxDynamicSharedMemorySize,
                             smem_bytes);
        configured = 1;
    }

    transpose_ctx<<<NBATCH * 512, 256>>>(context_v);

    // 65536 points total, 4 points (32 point-corner units) per block
    decoder_kernel<<<(NBATCH * NPTS) / NP, THREADS, smem_bytes>>>(
        qw, mask, grid, affine,
        w00, b00, w01, b01, w02, b02,
        w10, b10, w11, b11, w12, b12,
        wpo, bpo, out);
}

// round 10
// speedup vs baseline: 2.7322x; 2.3932x over previous
#include <cuda_runtime.h>
#include <cuda_bf16.h>
#include <cstdint>

// ----------------------------------------------------------------------------
// Decoder_61237643706389 — mma.sync (HMMA bf16, sm_80-compatible PTX) path.
// tcgen05 is unavailable (harness compiles via compute_103 virtual arch), so
// the tensor pipe is driven with m16n8k16 bf16 mma, register accumulators.
// Per block: 8 points x 8 corners = 64 units; D[96,64] = W[96,K] x H[K,64],
// bf16 hi/lo split (A_hi*B_hi + A_hi*B_lo + A_lo*B_hi) for fp32-grade accuracy.
// Weights pre-packed into exact mma A-fragment layout by a prep kernel.
// ----------------------------------------------------------------------------

typedef unsigned int       u32;
typedef unsigned long long u64;

#define G        32
#define NBATCH   2
#define CCH      96
#define NPTS     32768
#define OUTC     45
#define NP       8
#define NU       64
#define THREADS  256

#define S_H      100            // H row stride in 32-bit words (== 4 mod 32)
#define YSTR     66             // yf row stride in floats

// dynamic smem layout (bytes)
#define SM_HHI   0                          // H hi: 64 rows x 100 words
#define SM_HLO   25600                      // H lo
#define SM_YF    51200                      // yf fp32 [96][YSTR]
#define SM_TOT   (51200 + CCH * YSTR * 4)   // 76544

// Transposed context features: [B][x][y][z][C], contiguous C.
__device__ float g_cvt[NBATCH * NPTS * CCH];
// Pre-packed A fragments: idx = ((sg*6 + mtg)*2 + split)*32 + lane, uint4 each.
// sg: global k16 step (46 total over 6 layers), mtg: m-tile 0..5, split: hi/lo.
#define NSG 46
__device__ uint4 g_wf[NSG * 12 * 32];

__device__ __forceinline__ float silu_f(float x) {
    return x / (1.0f + __expf(-x));
}
__device__ __forceinline__ unsigned short bfbits(float v) {
    __nv_bfloat16 h = __float2bfloat16(v);
    return *reinterpret_cast<unsigned short*>(&h);
}
__device__ __forceinline__ float bfval(float v) {   // value of bf16(v)
    return __bfloat162float(__float2bfloat16(v));
}

__device__ __forceinline__ void mma16816(float (&d)[4], uint4 a, u32 b0, u32 b1) {
    asm volatile(
        "mma.sync.aligned.m16n8k16.row.col.f32.bf16.bf16.f32 "
        "{%0,%1,%2,%3}, {%4,%5,%6,%7}, {%8,%9}, {%0,%1,%2,%3};"
        : "+f"(d[0]), "+f"(d[1]), "+f"(d[2]), "+f"(d[3])
        : "r"(a.x), "r"(a.y), "r"(a.z), "r"(a.w), "r"(b0), "r"(b1));
}

// write one activation value into H (bf16 hi/lo halfwords). u = unit, k = row.
__device__ __forceinline__ void write_h(char* sm, int u, int k, float v) {
    float hi = bfval(v);
    int off = (u * S_H + (k >> 1)) * 4 + (k & 1) * 2;
    *reinterpret_cast<unsigned short*>(sm + SM_HHI + off) = bfbits(v);
    *reinterpret_cast<unsigned short*>(sm + SM_HLO + off) = bfbits(v - hi);
}

// ---------------------------------------------------------------------------
// Prep: transpose context_v [B,C,S] -> g_cvt [B,S,C].
// ---------------------------------------------------------------------------
__global__ void transpose_ctx(const float* __restrict__ src) {
    __shared__ float tile[CCH][65];
    int bs = blockIdx.x;
    int b  = bs >> 9;
    int s0 = (bs & 511) * 64;
    for (int idx = threadIdx.x; idx < CCH * 64; idx += blockDim.x) {
        int c = idx >> 6, so = idx & 63;
        tile[c][so] = src[((long)(b * CCH + c) << 15) + s0 + so];
    }
    __syncthreads();
    for (int idx = threadIdx.x; idx < CCH * 64; idx += blockDim.x) {
        int so = idx / CCH, c = idx % CCH;
        g_cvt[(((long)b << 15) + s0 + so) * CCH + c] = tile[c][so];
    }
}

// ---------------------------------------------------------------------------
// Prep: pack weights into mma A-fragment layout, bf16 hi/lo split.
// A[m][k] = W[k][m]; fragment regs per PTX m16n8k16 row-major A:
//   a0:(r, k0..k0+1) a1:(r+8, k0..) a2:(r, k0+8..) a3:(r+8, k0+8..),
//   r = mtg*16 + lane/4, k0 = s_local*16 + 2*(lane%4).
// ---------------------------------------------------------------------------
__global__ void conv_frags(const float* __restrict__ w00, const float* __restrict__ w01,
                           const float* __restrict__ w02, const float* __restrict__ w10,
                           const float* __restrict__ w11, const float* __restrict__ w12) {
    int idx = blockIdx.x * blockDim.x + threadIdx.x;
    if (idx >= NSG * 12 * 32) return;
    int lane = idx & 31;
    int t = idx >> 5;
    int split = t & 1; t >>= 1;
    int mtg = t % 6;
    int sg = t / 6;
    const float* W; int K; int sb;
    if      (sg < 11) { W = w00; K = 174; sb = 0;  }
    else if (sg < 17) { W = w01; K = 96;  sb = 11; }
    else if (sg < 23) { W = w02; K = 96;  sb = 17; }
    else if (sg < 34) { W = w10; K = 174; sb = 23; }
    else if (sg < 40) { W = w11; K = 96;  sb = 34; }
    else              { W = w12; K = 96;  sb = 40; }
    int k0 = (sg - sb) * 16 + 2 * (lane & 3);
    int m0 = mtg * 16 + (lane >> 2);

    auto get = [&](int k, int m) -> u32 {
        float v = (k < K) ? __ldg(W + k * 96 + m) : 0.0f;
        if (split) v = v - bfval(v);
        return (u32)bfbits(v);
    };
    uint4 r;
    r.x = get(k0, m0)     | (get(k0 + 1, m0)     << 16);
    r.y = get(k0, m0 + 8) | (get(k0 + 1, m0 + 8) << 16);
    r.z = get(k0 + 8, m0)     | (get(k0 + 9, m0)     << 16);
    r.w = get(k0 + 8, m0 + 8) | (get(k0 + 9, m0 + 8) << 16);
    g_wf[idx] = r;
}

// ---------------------------------------------------------------------------
// One MLP layer on tensor cores.
// ---------------------------------------------------------------------------
template <int K16, int BASE, bool RES, bool WRITEH>
__device__ __forceinline__ void run_layer(char* sm, const float* __restrict__ bias,
                                          int lane, int wm, int wn) {
    float* yf = reinterpret_cast<float*>(sm + SM_YF);
    const u32* Hh = reinterpret_cast<const u32*>(sm + SM_HHI);
    const u32* Hl = reinterpret_cast<const u32*>(sm + SM_HLO);

    float d[3][2][4];
#pragma unroll
    for (int mt = 0; mt < 3; ++mt) {
        int r0 = wm * 48 + mt * 16 + (lane >> 2);
        float blo = __ldg(bias + r0), bhi = __ldg(bias + r0 + 8);
#pragma unroll
        for (int nt = 0; nt < 2; ++nt) {
            d[mt][nt][0] = blo; d[mt][nt][1] = blo;
            d[mt][nt][2] = bhi; d[mt][nt][3] = bhi;
        }
    }

    const uint4* ap = g_wf + (size_t)((BASE * 6 + wm * 3) * 2) * 32 + lane;
    uint4 ah[3], al[3];
#pragma unroll
    for (int mt = 0; mt < 3; ++mt) {
        ah[mt] = __ldg(ap + mt * 64);
        al[mt] = __ldg(ap + mt * 64 + 32);
    }
    const int nrow = wn * 16 + (lane >> 2);
    const int lq = lane & 3;

#pragma unroll 2
    for (int s = 0; s < K16; ++s) {
        u32 bh[2][2], bl[2][2];
#pragma unroll
        for (int nt = 0; nt < 2; ++nt) {
            int w = (nrow + nt * 8) * S_H + s * 8 + lq;
            bh[nt][0] = Hh[w]; bh[nt][1] = Hh[w + 4];
            bl[nt][0] = Hl[w]; bl[nt][1] = Hl[w + 4];
        }
        uint4 ahn[3], aln[3];
        if (s + 1 < K16) {
            const uint4* apn = ap + (size_t)(s + 1) * 384;
#pragma unroll
            for (int mt = 0; mt < 3; ++mt) {
                ahn[mt] = __ldg(apn + mt * 64);
                aln[mt] = __ldg(apn + mt * 64 + 32);
            }
        }
#pragma unroll
        for (int mt = 0; mt < 3; ++mt)
#pragma unroll
            for (int nt = 0; nt < 2; ++nt) {
                mma16816(d[mt][nt], ah[mt], bh[nt][0], bh[nt][1]);
                mma16816(d[mt][nt], ah[mt], bl[nt][0], bl[nt][1]);
                mma16816(d[mt][nt], al[mt], bh[nt][0], bh[nt][1]);
            }
        if (s + 1 < K16) {
#pragma unroll
            for (int mt = 0; mt < 3; ++mt) { ah[mt] = ahn[mt]; al[mt] = aln[mt]; }
        }
    }
    __syncthreads();   // all warps done reading H before overwriting

    // epilogue: bias already in acc; silu (+residual) -> H / yf
#pragma unroll
    for (int mt = 0; mt < 3; ++mt) {
        int r0 = wm * 48 + mt * 16 + (lane >> 2);
#pragma unroll
        for (int nt = 0; nt < 2; ++nt) {
            int c0 = wn * 16 + nt * 8 + 2 * lq;
            int rr[4] = { r0, r0, r0 + 8, r0 + 8 };
            int cc[4] = { c0, c0 + 1, c0, c0 + 1 };
#pragma unroll
            for (int e = 0; e < 4; ++e) {
                float h = silu_f(d[mt][nt][e]);
                if (RES) {
                    h += yf[rr[e] * YSTR + cc[e]];
                    yf[rr[e] * YSTR + cc[e]] = h;
                }
                if (WRITEH) write_h(sm, cc[e], rr[e], h);
            }
        }
    }
    __syncthreads();
}

// ---------------------------------------------------------------------------
// Main kernel: 8 points x 8 corners = 64 units, 256 threads (8 warps).
// ---------------------------------------------------------------------------
__global__ void __launch_bounds__(THREADS)
decoder_kernel(const float* __restrict__ qw_g,
               const int* __restrict__ mask_g,
               const float* __restrict__ grid_g,
               const float* __restrict__ affine_g,
               const float* __restrict__ b00, const float* __restrict__ b01,
               const float* __restrict__ b02, const float* __restrict__ b10,
               const float* __restrict__ b11, const float* __restrict__ b12,
               const float* __restrict__ wpo, const float* __restrict__ bpo,
               float* __restrict__ out) {
    const int tid = threadIdx.x;
    const int pg0 = blockIdx.x * NP;
    const int b   = pg0 >> 15;

    extern __shared__ char sm[];
    float* yf = reinterpret_cast<float*>(sm + SM_YF);

    __shared__ float s_inv[12];
    __shared__ float s_qw[NP][3];
    __shared__ float s_sub[NP][3];
    __shared__ float s_mf[NP];
    __shared__ int   s_bot[NP][3];
    __shared__ int   s_voff[NU];
    __shared__ float s_cw[NU][3];
    __shared__ float s_wtri[NU];
    __shared__ float s_red[CCH * NP];

    // --- affine inverse (last row assumed [0,0,0,1]) ---
    if (tid == 0) {
        const float* A = affine_g + b * 16;
        float a00 = A[0], a01 = A[1], a02 = A[2],  t0 = A[3];
        float a10 = A[4], a11 = A[5], a12 = A[6],  t1 = A[7];
        float a20 = A[8], a21 = A[9], a22 = A[10], t2 = A[11];
        float c00 = a11 * a22 - a12 * a21;
        float c01 = a02 * a21 - a01 * a22;
        float c02 = a01 * a12 - a02 * a11;
        float det = a00 * c00 + a10 * c01 + a20 * c02;
        float id  = 1.0f / det;
        float i00 = c00 * id, i01 = c01 * id, i02 = c02 * id;
        float i10 = (a12 * a20 - a10 * a22) * id;
        float i11 = (a00 * a22 - a02 * a20) * id;
        float i12 = (a02 * a10 - a00 * a12) * id;
        float i20 = (a10 * a21 - a11 * a20) * id;
        float i21 = (a01 * a20 - a00 * a21) * id;
        float i22 = (a00 * a11 - a01 * a10) * id;
        s_inv[0] = i00; s_inv[1] = i01; s_inv[2]  = i02; s_inv[3]  = -(i00 * t0 + i01 * t1 + i02 * t2);
        s_inv[4] = i10; s_inv[5] = i11; s_inv[6]  = i12; s_inv[7]  = -(i10 * t0 + i11 * t1 + i12 * t2);
        s_inv[8] = i20; s_inv[9] = i21; s_inv[10] = i22; s_inv[11] = -(i20 * t0 + i21 * t1 + i22 * t2);
    }
    __syncthreads();

    // --- per-point setup ---
    if (tid < NP) {
        int pg = pg0 + tid;
        float mf = (mask_g[pg] != 0) ? 1.0f : 0.0f;
        const float* qp = qw_g + (mf != 0.0f ? (long)pg * 3
                                             : ((long)b * NPTS + NPTS / 2) * 3);
        float q0 = qp[0], q1 = qp[1], q2 = qp[2];
        s_qw[tid][0] = q0; s_qw[tid][1] = q1; s_qw[tid][2] = q2;
        s_mf[tid] = mf;
#pragma unroll
        for (int r = 0; r < 3; ++r) {
            float qv = s_inv[r * 4 + 0] * q0 + s_inv[r * 4 + 1] * q1 +
                       s_inv[r * 4 + 2] * q2 + s_inv[r * 4 + 3];
            float fb = floorf(qv);
            s_bot[tid][r] = (int)fb;
            s_sub[tid][r] = qv - fb;
        }
    }
    __syncthreads();

    // --- per-unit voxel, cw, trilinear weight ---
    if (tid < NU) {
        int pt = tid >> 3, c = tid & 7;
        int o0 = (c >> 2) & 1, o1 = (c >> 1) & 1, o2 = c & 1;
        int i0 = min(max(s_bot[pt][0] + o0, 0), G - 1);
        int i1 = min(max(s_bot[pt][1] + o1, 0), G - 1);
        int i2 = min(max(s_bot[pt][2] + o2, 0), G - 1);
        int sp = (i0 * G + i1) * G + i2;
        s_voff[tid] = (b * NPTS + sp) * CCH;
        const float* gp = grid_g + (long)(b * NPTS + sp) * 3;
        s_cw[tid][0] = gp[0]; s_cw[tid][1] = gp[1]; s_cw[tid][2] = gp[2];
        float ww0 = o0 ? s_sub[pt][0] : 1.0f - s_sub[pt][0];
        float ww1 = o1 ? s_sub[pt][1] : 1.0f - s_sub[pt][1];
        float ww2 = o2 ? s_sub[pt][2] : 1.0f - s_sub[pt][2];
        s_wtri[tid] = ww0 * ww1 * ww2;
    }
    __syncthreads();

    // --- feature gather: yf + H rows 0..95 (channel pairs) ---
    u32* Hh = reinterpret_cast<u32*>(sm + SM_HHI);
    u32* Hl = reinterpret_cast<u32*>(sm + SM_HLO);
#pragma unroll
    for (int rep = 0; rep < 12; ++rep) {
        int idx = tid + rep * THREADS;       // < 3072 = 64u * 48 ch-pairs
        int u = idx / 48, cp = idx % 48;
        float mf = s_mf[u >> 3];
        const float* src = g_cvt + s_voff[u] + 2 * cp;
        float vx = src[0] * mf, vy = src[1] * mf;
        yf[(2 * cp) * YSTR + u]     = vx;
        yf[(2 * cp + 1) * YSTR + u] = vy;
        Hh[u * S_H + cp] = (u32)bfbits(vx) | ((u32)bfbits(vy) << 16);
        Hl[u * S_H + cp] = (u32)bfbits(vx - bfval(vx)) | ((u32)bfbits(vy - bfval(vy)) << 16);
    }
    // --- H rows 96..101: cw, qw ---
    {
        int idx = tid;                       // 384 entries, 2 reps
#pragma unroll
        for (int it = 0; it < 2; ++it, idx += THREADS) {
            if (idx < 384) {
                int u = idx / 6, r = idx % 6;
                float mf = s_mf[u >> 3];
                float v = (r < 3) ? s_cw[u][r] : s_qw[u >> 3][r - 3];
                write_h(sm, u, 96 + r, v * mf);
            }
        }
    }
    // --- H rows 102..173: fourier ---
#pragma unroll
    for (int it = 0; it < 9; ++it) {
        int idx = tid + it * THREADS;        // < 2304
        int u = idx / 36, e = idx % 36;
        int a = e / 12, j = e % 12;
        int pt = u >> 3, c = u & 7;
        int off = (a == 0) ? ((c >> 2) & 1) : ((a == 1) ? ((c >> 1) & 1) : (c & 1));
        float rel = (s_sub[pt][a] - (float)off + 1.0f) * 0.5f;
        float f = exp2f((float)j * 0.13208020839342967f);   // 3^(j/12)
        float ang = 6.283185307179586f * f * rel;
        float sv, cv;
        __sincosf(ang, &sv, &cv);
        float mf = s_mf[pt];
        write_h(sm, u, 102 + a * 24 + j,      sv * mf);
        write_h(sm, u, 102 + a * 24 + 12 + j, cv * mf);
    }
    // --- H rows 174..175: zero pad (word 87 per unit) ---
    if (tid < NU) {
        Hh[tid * S_H + 87] = 0;
        Hl[tid * S_H + 87] = 0;
    }
    __syncthreads();

    // --- 6 MLP layers on tensor cores ---
    const int lane = tid & 31;
    const int w    = tid >> 5;
    const int wm   = w & 1;       // m-half (48 channels)
    const int wn   = w >> 1;      // n-quarter (16 units)

    run_layer<11, 0,  false, true >(sm, b00, lane, wm, wn);
    run_layer<6,  11, false, true >(sm, b01, lane, wm, wn);
    run_layer<6,  17, true,  true >(sm, b02, lane, wm, wn);
    run_layer<11, 23, false, true >(sm, b10, lane, wm, wn);
    run_layer<6,  34, false, true >(sm, b11, lane, wm, wn);
    run_layer<6,  40, true,  false>(sm, b12, lane, wm, wn);

    // --- trilinear reduce: ybar = sum_c wtri_c * y_c (sum wtri == 1) ---
#pragma unroll
    for (int it = 0; it < 3; ++it) {
        int idx = tid + it * THREADS;        // < 768
        int ch = idx >> 3, pt = idx & 7;
        float acc = 0.0f;
#pragma unroll
        for (int c = 0; c < 8; ++c)
            acc += s_wtri[pt * 8 + c] * yf[ch * YSTR + pt * 8 + c];
        s_red[ch * NP + pt] = acc;
    }
    __syncthreads();

    // --- post layer: 96 -> 45, 8 points ---
    if (tid < OUTC) {
        float a[NP];
        float bv = __ldg(bpo + tid);
#pragma unroll
        for (int p = 0; p < NP; ++p) a[p] = bv;
#pragma unroll 4
        for (int k = 0; k < CCH; ++k) {
            float wv = __ldg(wpo + k * OUTC + tid);
#pragma unroll
            for (int p = 0; p < NP; ++p)
                a[p] = fmaf(s_red[k * NP + p], wv, a[p]);
        }
        int n0 = pg0 & (NPTS - 1);
        long base = ((long)b * OUTC + tid) * NPTS + n0;
#pragma unroll
        for (int p = 0; p < NP; ++p)
            out[base + p] = a[p];
    }
}

// ---------------------------------------------------------------------------
extern "C" void kernel_launch(void* const* d_in, const int* in_sizes, int n_in,
                              void* d_out, int out_size) {
    const float* context_v = (const float*)d_in[0];
    const float* grid      = (const float*)d_in[1];
    const float* qw        = (const float*)d_in[2];
    const int*   mask      = (const int*)d_in[3];
    const float* affine    = (const float*)d_in[4];
    const float* w00 = (const float*)d_in[8],  *b00 = (const float*)d_in[9];
    const float* w01 = (const float*)d_in[10], *b01 = (const float*)d_in[11];
    const float* w02 = (const float*)d_in[12], *b02 = (const float*)d_in[13];
    const float* w10 = (const float*)d_in[14], *b10 = (const float*)d_in[15];
    const float* w11 = (const float*)d_in[16], *b11 = (const float*)d_in[17];
    const float* w12 = (const float*)d_in[18], *b12 = (const float*)d_in[19];
    const float* wpo = (const float*)d_in[20], *bpo = (const float*)d_in[21];
    float* out = (float*)d_out;

    static int configured = 0;
    if (!configured) {
        cudaFuncSetAttribute(decoder_kernel,
                             cudaFuncAttributeMaxDynamicSharedMemorySize,
                             SM_TOT);
        configured = 1;
    }

    transpose_ctx<<<NBATCH * 512, 256>>>(context_v);
    conv_frags<<<(NSG * 12 * 32 + 255) / 256, 256>>>(w00, w01, w02, w10, w11, w12);
    decoder_kernel<<<(NBATCH * NPTS) / NP, THREADS, SM_TOT>>>(
        qw, mask, grid, affine,
        b00, b01, b02, b10, b11, b12,
        wpo, bpo, out);
}